// round 14
// baseline (speedup 1.0000x reference)
#include <cuda_runtime.h>

// ButterflyLinear, fused single kernel, third attempt with the failure
// modes of R5/R6 (register hoisting, redundant-fold L2 traffic) and R9/R12
// (grid-barrier serialization) both engineered out:
//  - T_PER=64 -> only 512 blocks -> fold redundancy is 49MB of L2 reads
//    (~4us, overlapped), and ALL blocks are resident in one wave at
//    4 CTA/SM so the fold happens once, concurrently, no barrier.
//  - fold loads chunked 4 stages at a time (8 float4 live) so ptxas cannot
//    hoist 24 loads into 96 registers (the R5 killer).
//  - streaming body: loop of chunk-of-8 front-batched loads (MLP_p1=8,
//    the measured optimum; 16 bought nothing at R13).
// Math: stage 0 pairs (j, j^1); stages 1..11 all pair (j, j^2) => the
// 12-stage network is block-diagonal in 4-element groups:
//   out[t, 4g..4g+3] = A_g * x[t, 4g..4g+3] + bias.

#define TOKENS 8192
#define NCOLS  4096
#define DEPTH  12
#define GROUPS (NCOLS / 4)   // 1024
#define PAIRS  (NCOLS / 2)   // 2048 factor pairs per stage
#define T_PER  64            // tokens per thread -> (4,128) = 512 blocks

// factors layout: F[stage][pair][c][d] as float4 per pair:
//   f.x=f[0][0], f.y=f[0][1], f.z=f[1][0], f.w=f[1][1]
// Stage semantics: y[d] = sum_c pair_in[c] * f[c][d]

// row-major 4x4 apply: r[d] = b[d] + sum_e a[d][e] * v[e]
#define QUADR(rr, vv)                                                       \
    rr.x = b.x + vv.x*a00 + vv.y*a01 + vv.z*a02 + vv.w*a03;                 \
    rr.y = b.y + vv.x*a10 + vv.y*a11 + vv.z*a12 + vv.w*a13;                 \
    rr.z = b.z + vv.x*a20 + vv.y*a21 + vv.z*a22 + vv.w*a23;                 \
    rr.w = b.w + vv.x*a30 + vv.y*a31 + vv.z*a32 + vv.w*a33;

__global__ void __launch_bounds__(256, 4)
butterfly_fused(const float4* __restrict__ F4,
                const float4* __restrict__ x,
                const float4* __restrict__ bias4,
                float4* __restrict__ out) {
    int g  = blockIdx.x * blockDim.x + threadIdx.x;  // 0..GROUPS-1
    int t0 = blockIdx.y * T_PER;
    int j0 = 4 * g;

    // ---- fold the 12 stages into a 4x4 (row-major a{row}{col}) ----
    float a00, a01, a02, a03, a10, a11, a12, a13;
    float a20, a21, a22, a23, a30, a31, a32, a33;
    {
        float4 f0 = __ldg(F4 + 2 * g);
        float4 f1 = __ldg(F4 + 2 * g + 1);
        a00 = f0.x; a01 = f0.z; a02 = 0.f;  a03 = 0.f;
        a10 = f0.y; a11 = f0.w; a12 = 0.f;  a13 = 0.f;
        a20 = 0.f;  a21 = 0.f;  a22 = f1.x; a23 = f1.z;
        a30 = 0.f;  a31 = 0.f;  a32 = f1.y; a33 = f1.w;
    }
    // chunks of 4 stages: only 8 float4 factor regs live at a time
    #pragma unroll
    for (int c0 = 1; c0 < DEPTH; c0 += 4) {
        float4 fA[4], fB[4];
        #pragma unroll
        for (int k = 0; k < 4; k++) {
            int s = c0 + k;
            if (s < DEPTH) {
                int block = 1 << (s + 1);
                int pA = ((j0 >> (s + 1)) << s) | ((j0 & (block - 1)) >> 2);
                int pB = pA + (1 << (s - 1));
                fA[k] = __ldg(F4 + s * PAIRS + pA);
                fB[k] = __ldg(F4 + s * PAIRS + pB);
            }
        }
        #pragma unroll
        for (int k = 0; k < 4; k++) {
            int s = c0 + k;
            if (s < DEPTH) {
                float r0, r2;
                r0 = a00; r2 = a20; a00 = fA[k].x*r0 + fA[k].z*r2; a20 = fA[k].y*r0 + fA[k].w*r2;
                r0 = a01; r2 = a21; a01 = fA[k].x*r0 + fA[k].z*r2; a21 = fA[k].y*r0 + fA[k].w*r2;
                r0 = a02; r2 = a22; a02 = fA[k].x*r0 + fA[k].z*r2; a22 = fA[k].y*r0 + fA[k].w*r2;
                r0 = a03; r2 = a23; a03 = fA[k].x*r0 + fA[k].z*r2; a23 = fA[k].y*r0 + fA[k].w*r2;
                float r1, r3;
                r1 = a10; r3 = a30; a10 = fB[k].x*r1 + fB[k].z*r3; a30 = fB[k].y*r1 + fB[k].w*r3;
                r1 = a11; r3 = a31; a11 = fB[k].x*r1 + fB[k].z*r3; a31 = fB[k].y*r1 + fB[k].w*r3;
                r1 = a12; r3 = a32; a12 = fB[k].x*r1 + fB[k].z*r3; a32 = fB[k].y*r1 + fB[k].w*r3;
                r1 = a13; r3 = a33; a13 = fB[k].x*r1 + fB[k].z*r3; a33 = fB[k].y*r1 + fB[k].w*r3;
            }
        }
    }

    float4 b = bias4[g];

    const float4* xp = x   + (size_t)t0 * GROUPS + g;
    float4*       op = out + (size_t)t0 * GROUPS + g;

    // ---- stream T_PER tokens: chunk-of-8 front-batched loads (MLP_p1=8) ----
    for (int ii = 0; ii < T_PER; ii += 8) {
        float4 v0 = __ldcs(xp + (size_t)(ii + 0) * GROUPS);
        float4 v1 = __ldcs(xp + (size_t)(ii + 1) * GROUPS);
        float4 v2 = __ldcs(xp + (size_t)(ii + 2) * GROUPS);
        float4 v3 = __ldcs(xp + (size_t)(ii + 3) * GROUPS);
        float4 v4 = __ldcs(xp + (size_t)(ii + 4) * GROUPS);
        float4 v5 = __ldcs(xp + (size_t)(ii + 5) * GROUPS);
        float4 v6 = __ldcs(xp + (size_t)(ii + 6) * GROUPS);
        float4 v7 = __ldcs(xp + (size_t)(ii + 7) * GROUPS);

        float4 r0, r1, r2, r3;
        QUADR(r0, v0) QUADR(r1, v1) QUADR(r2, v2) QUADR(r3, v3)
        __stcs(op + (size_t)(ii + 0) * GROUPS, r0);
        __stcs(op + (size_t)(ii + 1) * GROUPS, r1);
        __stcs(op + (size_t)(ii + 2) * GROUPS, r2);
        __stcs(op + (size_t)(ii + 3) * GROUPS, r3);

        QUADR(r0, v4) QUADR(r1, v5) QUADR(r2, v6) QUADR(r3, v7)
        __stcs(op + (size_t)(ii + 4) * GROUPS, r0);
        __stcs(op + (size_t)(ii + 5) * GROUPS, r1);
        __stcs(op + (size_t)(ii + 6) * GROUPS, r2);
        __stcs(op + (size_t)(ii + 7) * GROUPS, r3);
    }
}

// ---------------------------------------------------------------------------
extern "C" void kernel_launch(void* const* d_in, const int* in_sizes, int n_in,
                              void* d_out, int out_size) {
    const float* x = nullptr;
    const float* factors = nullptr;
    const float* bias = nullptr;
    for (int i = 0; i < n_in; i++) {
        if (in_sizes[i] == TOKENS * NCOLS)            x = (const float*)d_in[i];
        else if (in_sizes[i] == DEPTH * PAIRS * 4)    factors = (const float*)d_in[i];
        else if (in_sizes[i] == NCOLS)                bias = (const float*)d_in[i];
    }

    dim3 grid(GROUPS / 256, TOKENS / T_PER);   // (4, 128) = 512 blocks
    butterfly_fused<<<grid, 256>>>((const float4*)factors,
                                   (const float4*)x,
                                   (const float4*)bias,
                                   (float4*)d_out);
}

// round 15
// speedup vs baseline: 1.0728x; 1.0728x over previous
#include <cuda_runtime.h>

// ButterflyLinear: 12 butterfly stages on N=4096, TOKENS=8192.
// Stage 0 pairs (j, j^1); stages 1..11 all pair (j, j^2) => transform is
// block-diagonal in 4-element groups. Kernel 1 folds per-group 4x4s
// (column-parallel, 4096 threads). Kernel 2 streams out = blockdiag(A)*x + b.
// This is R11 (best: 45.8us) with ONE change: output stores use default
// write-back policy instead of .cs, letting the 126MB L2 buffer the 128MB
// output and drain writes in long bursts (fewer HBM R/W turnarounds).
// Reads keep .cs (evict-first) so they don't displace the dirty out lines.

#define TOKENS 8192
#define NCOLS  4096
#define DEPTH  12
#define GROUPS (NCOLS / 4)   // 1024
#define PAIRS  (NCOLS / 2)   // 2048 factor pairs per stage
#define T_PER  8             // tokens per thread -> 4096 blocks

// Scratch: 1024 groups x 4 columns (each column = float4) = 64 KB.
// g_C[g*4+e] = (A[0][e], A[1][e], A[2][e], A[3][e])
__device__ float4 g_C[GROUPS * 4];

// ---------------------------------------------------------------------------
// Kernel 1: one thread per (group, column); column-separable fold with
// front-batched MLP=24 loads (one DRAM round-trip).
// factors layout: F[stage][pair][c][d] as float4 per pair:
//   f.x=f[0][0], f.y=f[0][1], f.z=f[1][0], f.w=f[1][1]
// Stage semantics: y[d] = sum_c pair_in[c] * f[c][d]
// ---------------------------------------------------------------------------
__global__ void butterfly_precompute(const float4* __restrict__ F4) {
    int t = blockIdx.x * blockDim.x + threadIdx.x;   // 0..4095
    int g = t >> 2;
    int e = t & 3;
    int j0 = 4 * g;

    float4 fa[DEPTH], fb[DEPTH];
    fa[0] = F4[2 * g];
    fb[0] = F4[2 * g + 1];
    #pragma unroll
    for (int s = 1; s < DEPTH; s++) {
        int block = 1 << (s + 1);
        int pA = ((j0 >> (s + 1)) << s) | ((j0 & (block - 1)) >> 2);
        int pB = pA + (1 << (s - 1));
        fa[s] = F4[s * PAIRS + pA];
        fb[s] = F4[s * PAIRS + pB];
    }

    float A0, A1, A2, A3;
    {
        float4 f0 = fa[0], f1 = fb[0];
        bool lo = (e < 2);
        float4 f = lo ? f0 : f1;
        float u = (e & 1) ? f.z : f.x;
        float v = (e & 1) ? f.w : f.y;
        A0 = lo ? u : 0.f;
        A1 = lo ? v : 0.f;
        A2 = lo ? 0.f : u;
        A3 = lo ? 0.f : v;
    }

    #pragma unroll
    for (int s = 1; s < DEPTH; s++) {
        float a00 = fa[s].x, a01 = fa[s].y, a10 = fa[s].z, a11 = fa[s].w;
        float b00 = fb[s].x, b01 = fb[s].y, b10 = fb[s].z, b11 = fb[s].w;
        float r0 = A0, r1 = A1, r2 = A2, r3 = A3;
        A0 = a00 * r0 + a10 * r2;
        A2 = a01 * r0 + a11 * r2;
        A1 = b00 * r1 + b10 * r3;
        A3 = b01 * r1 + b11 * r3;
    }

    g_C[t] = make_float4(A0, A1, A2, A3);
}

// ---------------------------------------------------------------------------
// Kernel 2: out[t, group g] = A_g * x[t, g] + bias_g (column-major A):
//   r = b + v.x*c0 + v.y*c1 + v.z*c2 + v.w*c3
// All 8 token loads issued before any compute/store: MLP_p1 = 8.
// Stores: default write-back (L2-buffered).
// ---------------------------------------------------------------------------
__global__ void __launch_bounds__(256, 4)
butterfly_apply(const float4* __restrict__ x,
                const float4* __restrict__ bias4,
                float4* __restrict__ out) {
    int g  = blockIdx.x * blockDim.x + threadIdx.x;  // 0..GROUPS-1
    int t0 = blockIdx.y * T_PER;

    const float4* xp = x   + (size_t)t0 * GROUPS + g;
    float4*       op = out + (size_t)t0 * GROUPS + g;

    // ---- all 8 loads in flight before anything else ----
    float4 v0 = __ldcs(xp + 0 * GROUPS);
    float4 v1 = __ldcs(xp + 1 * GROUPS);
    float4 v2 = __ldcs(xp + 2 * GROUPS);
    float4 v3 = __ldcs(xp + 3 * GROUPS);
    float4 v4 = __ldcs(xp + 4 * GROUPS);
    float4 v5 = __ldcs(xp + 5 * GROUPS);
    float4 v6 = __ldcs(xp + 6 * GROUPS);
    float4 v7 = __ldcs(xp + 7 * GROUPS);

    float4 c0 = g_C[g * 4 + 0];
    float4 c1 = g_C[g * 4 + 1];
    float4 c2 = g_C[g * 4 + 2];
    float4 c3 = g_C[g * 4 + 3];
    float4 b  = bias4[g];

    float4 r0, r1, r2, r3;
    r0.x = b.x + v0.x*c0.x + v0.y*c1.x + v0.z*c2.x + v0.w*c3.x;
    r0.y = b.y + v0.x*c0.y + v0.y*c1.y + v0.z*c2.y + v0.w*c3.y;
    r0.z = b.z + v0.x*c0.z + v0.y*c1.z + v0.z*c2.z + v0.w*c3.z;
    r0.w = b.w + v0.x*c0.w + v0.y*c1.w + v0.z*c2.w + v0.w*c3.w;

    r1.x = b.x + v1.x*c0.x + v1.y*c1.x + v1.z*c2.x + v1.w*c3.x;
    r1.y = b.y + v1.x*c0.y + v1.y*c1.y + v1.z*c2.y + v1.w*c3.y;
    r1.z = b.z + v1.x*c0.z + v1.y*c1.z + v1.z*c2.z + v1.w*c3.z;
    r1.w = b.w + v1.x*c0.w + v1.y*c1.w + v1.z*c2.w + v1.w*c3.w;

    r2.x = b.x + v2.x*c0.x + v2.y*c1.x + v2.z*c2.x + v2.w*c3.x;
    r2.y = b.y + v2.x*c0.y + v2.y*c1.y + v2.z*c2.y + v2.w*c3.y;
    r2.z = b.z + v2.x*c0.z + v2.y*c1.z + v2.z*c2.z + v2.w*c3.z;
    r2.w = b.w + v2.x*c0.w + v2.y*c1.w + v2.z*c2.w + v2.w*c3.w;

    r3.x = b.x + v3.x*c0.x + v3.y*c1.x + v3.z*c2.x + v3.w*c3.x;
    r3.y = b.y + v3.x*c0.y + v3.y*c1.y + v3.z*c2.y + v3.w*c3.y;
    r3.z = b.z + v3.x*c0.z + v3.y*c1.z + v3.z*c2.z + v3.w*c3.z;
    r3.w = b.w + v3.x*c0.w + v3.y*c1.w + v3.z*c2.w + v3.w*c3.w;

    op[0 * GROUPS] = r0;
    op[1 * GROUPS] = r1;
    op[2 * GROUPS] = r2;
    op[3 * GROUPS] = r3;

    r0.x = b.x + v4.x*c0.x + v4.y*c1.x + v4.z*c2.x + v4.w*c3.x;
    r0.y = b.y + v4.x*c0.y + v4.y*c1.y + v4.z*c2.y + v4.w*c3.y;
    r0.z = b.z + v4.x*c0.z + v4.y*c1.z + v4.z*c2.z + v4.w*c3.z;
    r0.w = b.w + v4.x*c0.w + v4.y*c1.w + v4.z*c2.w + v4.w*c3.w;

    r1.x = b.x + v5.x*c0.x + v5.y*c1.x + v5.z*c2.x + v5.w*c3.x;
    r1.y = b.y + v5.x*c0.y + v5.y*c1.y + v5.z*c2.y + v5.w*c3.y;
    r1.z = b.z + v5.x*c0.z + v5.y*c1.z + v5.z*c2.z + v5.w*c3.z;
    r1.w = b.w + v5.x*c0.w + v5.y*c1.w + v5.z*c2.w + v5.w*c3.w;

    r2.x = b.x + v6.x*c0.x + v6.y*c1.x + v6.z*c2.x + v6.w*c3.x;
    r2.y = b.y + v6.x*c0.y + v6.y*c1.y + v6.z*c2.y + v6.w*c3.y;
    r2.z = b.z + v6.x*c0.z + v6.y*c1.z + v6.z*c2.z + v6.w*c3.z;
    r2.w = b.w + v6.x*c0.w + v6.y*c1.w + v6.z*c2.w + v6.w*c3.w;

    r3.x = b.x + v7.x*c0.x + v7.y*c1.x + v7.z*c2.x + v7.w*c3.x;
    r3.y = b.y + v7.x*c0.y + v7.y*c1.y + v7.z*c2.y + v7.w*c3.y;
    r3.z = b.z + v7.x*c0.z + v7.y*c1.z + v7.z*c2.z + v7.w*c3.z;
    r3.w = b.w + v7.x*c0.w + v7.y*c1.w + v7.z*c2.w + v7.w*c3.w;

    op[4 * GROUPS] = r0;
    op[5 * GROUPS] = r1;
    op[6 * GROUPS] = r2;
    op[7 * GROUPS] = r3;
}

// ---------------------------------------------------------------------------
extern "C" void kernel_launch(void* const* d_in, const int* in_sizes, int n_in,
                              void* d_out, int out_size) {
    const float* x = nullptr;
    const float* factors = nullptr;
    const float* bias = nullptr;
    for (int i = 0; i < n_in; i++) {
        if (in_sizes[i] == TOKENS * NCOLS)            x = (const float*)d_in[i];
        else if (in_sizes[i] == DEPTH * PAIRS * 4)    factors = (const float*)d_in[i];
        else if (in_sizes[i] == NCOLS)                bias = (const float*)d_in[i];
    }

    // Kernel 1: 4096 threads = 1 per (group, column).
    butterfly_precompute<<<32, 128>>>((const float4*)factors);

    // Kernel 2: (4, 1024) = 4096 blocks, 8 tokens per thread.
    dim3 grid(GROUPS / 256, TOKENS / T_PER);
    butterfly_apply<<<grid, 256>>>((const float4*)x,
                                   (const float4*)bias,
                                   (float4*)d_out);
}

// round 16
// speedup vs baseline: 1.1435x; 1.0659x over previous
#include <cuda_runtime.h>

// ButterflyLinear: 12 butterfly stages on N=4096, TOKENS=8192.
// Stage 0 pairs (j, j^1); stages 1..11 all pair (j, j^2) => transform is
// block-diagonal in 4-element groups. Kernel 1 folds per-group 4x4s
// (column-parallel, 4096 threads). Kernel 2 streams out = blockdiag(A)*x + b.
//
// FINAL FORM (= R11 champion, 45.8us):
//  - apply: MLP_p1=8 (all 8 token loads front-batched), .cs loads AND .cs
//    stores (R15 proved write-back stores defer 128MB of dirty-line evictions
//    into the next replay's read path: +3.9us), launch_bounds(256,4).
//  - 72.9% DRAM = measured mixed-R/W ceiling (invariant across occ 22-63%,
//    MLP 4-16, batch 2-8: 15 rounds of evidence).
//  - two-kernel structure: fusion/barrier alternatives all regressed
//    (R5,R6,R9,R12,R14) because redundant folds cost L2 BW and barriers
//    idle the grid; the second node costs only ~3us net.

#define TOKENS 8192
#define NCOLS  4096
#define DEPTH  12
#define GROUPS (NCOLS / 4)   // 1024
#define PAIRS  (NCOLS / 2)   // 2048 factor pairs per stage
#define T_PER  8             // tokens per thread -> 4096 blocks

// Scratch: 1024 groups x 4 columns (each column = float4) = 64 KB.
// g_C[g*4+e] = (A[0][e], A[1][e], A[2][e], A[3][e])
__device__ float4 g_C[GROUPS * 4];

// ---------------------------------------------------------------------------
// Kernel 1: one thread per (group, column); column-separable fold with
// front-batched MLP=24 loads (one DRAM round-trip). 128 blocks x 32 threads
// spreads the latency-bound prefix across 128 SMs.
// factors layout: F[stage][pair][c][d] as float4 per pair:
//   f.x=f[0][0], f.y=f[0][1], f.z=f[1][0], f.w=f[1][1]
// Stage semantics: y[d] = sum_c pair_in[c] * f[c][d]
// ---------------------------------------------------------------------------
__global__ void butterfly_precompute(const float4* __restrict__ F4) {
    int t = blockIdx.x * blockDim.x + threadIdx.x;   // 0..4095
    int g = t >> 2;
    int e = t & 3;
    int j0 = 4 * g;

    float4 fa[DEPTH], fb[DEPTH];
    fa[0] = F4[2 * g];
    fb[0] = F4[2 * g + 1];
    #pragma unroll
    for (int s = 1; s < DEPTH; s++) {
        int block = 1 << (s + 1);
        int pA = ((j0 >> (s + 1)) << s) | ((j0 & (block - 1)) >> 2);
        int pB = pA + (1 << (s - 1));
        fa[s] = F4[s * PAIRS + pA];
        fb[s] = F4[s * PAIRS + pB];
    }

    float A0, A1, A2, A3;
    {
        float4 f0 = fa[0], f1 = fb[0];
        bool lo = (e < 2);
        float4 f = lo ? f0 : f1;
        float u = (e & 1) ? f.z : f.x;
        float v = (e & 1) ? f.w : f.y;
        A0 = lo ? u : 0.f;
        A1 = lo ? v : 0.f;
        A2 = lo ? 0.f : u;
        A3 = lo ? 0.f : v;
    }

    #pragma unroll
    for (int s = 1; s < DEPTH; s++) {
        float a00 = fa[s].x, a01 = fa[s].y, a10 = fa[s].z, a11 = fa[s].w;
        float b00 = fb[s].x, b01 = fb[s].y, b10 = fb[s].z, b11 = fb[s].w;
        float r0 = A0, r1 = A1, r2 = A2, r3 = A3;
        A0 = a00 * r0 + a10 * r2;
        A2 = a01 * r0 + a11 * r2;
        A1 = b00 * r1 + b10 * r3;
        A3 = b01 * r1 + b11 * r3;
    }

    g_C[t] = make_float4(A0, A1, A2, A3);
}

// ---------------------------------------------------------------------------
// Kernel 2: out[t, group g] = A_g * x[t, g] + bias_g (column-major A):
//   r = b + v.x*c0 + v.y*c1 + v.z*c2 + v.w*c3
// All 8 token loads issued before any compute/store: MLP_p1 = 8.
// ---------------------------------------------------------------------------
__global__ void __launch_bounds__(256, 4)
butterfly_apply(const float4* __restrict__ x,
                const float4* __restrict__ bias4,
                float4* __restrict__ out) {
    int g  = blockIdx.x * blockDim.x + threadIdx.x;  // 0..GROUPS-1
    int t0 = blockIdx.y * T_PER;

    const float4* xp = x   + (size_t)t0 * GROUPS + g;
    float4*       op = out + (size_t)t0 * GROUPS + g;

    // ---- all 8 loads in flight before anything else ----
    float4 v0 = __ldcs(xp + 0 * GROUPS);
    float4 v1 = __ldcs(xp + 1 * GROUPS);
    float4 v2 = __ldcs(xp + 2 * GROUPS);
    float4 v3 = __ldcs(xp + 3 * GROUPS);
    float4 v4 = __ldcs(xp + 4 * GROUPS);
    float4 v5 = __ldcs(xp + 5 * GROUPS);
    float4 v6 = __ldcs(xp + 6 * GROUPS);
    float4 v7 = __ldcs(xp + 7 * GROUPS);

    float4 c0 = g_C[g * 4 + 0];
    float4 c1 = g_C[g * 4 + 1];
    float4 c2 = g_C[g * 4 + 2];
    float4 c3 = g_C[g * 4 + 3];
    float4 b  = bias4[g];

    float4 r0, r1, r2, r3;
    r0.x = b.x + v0.x*c0.x + v0.y*c1.x + v0.z*c2.x + v0.w*c3.x;
    r0.y = b.y + v0.x*c0.y + v0.y*c1.y + v0.z*c2.y + v0.w*c3.y;
    r0.z = b.z + v0.x*c0.z + v0.y*c1.z + v0.z*c2.z + v0.w*c3.z;
    r0.w = b.w + v0.x*c0.w + v0.y*c1.w + v0.z*c2.w + v0.w*c3.w;

    r1.x = b.x + v1.x*c0.x + v1.y*c1.x + v1.z*c2.x + v1.w*c3.x;
    r1.y = b.y + v1.x*c0.y + v1.y*c1.y + v1.z*c2.y + v1.w*c3.y;
    r1.z = b.z + v1.x*c0.z + v1.y*c1.z + v1.z*c2.z + v1.w*c3.z;
    r1.w = b.w + v1.x*c0.w + v1.y*c1.w + v1.z*c2.w + v1.w*c3.w;

    r2.x = b.x + v2.x*c0.x + v2.y*c1.x + v2.z*c2.x + v2.w*c3.x;
    r2.y = b.y + v2.x*c0.y + v2.y*c1.y + v2.z*c2.y + v2.w*c3.y;
    r2.z = b.z + v2.x*c0.z + v2.y*c1.z + v2.z*c2.z + v2.w*c3.z;
    r2.w = b.w + v2.x*c0.w + v2.y*c1.w + v2.z*c2.w + v2.w*c3.w;

    r3.x = b.x + v3.x*c0.x + v3.y*c1.x + v3.z*c2.x + v3.w*c3.x;
    r3.y = b.y + v3.x*c0.y + v3.y*c1.y + v3.z*c2.y + v3.w*c3.y;
    r3.z = b.z + v3.x*c0.z + v3.y*c1.z + v3.z*c2.z + v3.w*c3.z;
    r3.w = b.w + v3.x*c0.w + v3.y*c1.w + v3.z*c2.w + v3.w*c3.w;

    __stcs(op + 0 * GROUPS, r0);
    __stcs(op + 1 * GROUPS, r1);
    __stcs(op + 2 * GROUPS, r2);
    __stcs(op + 3 * GROUPS, r3);

    // v0..v3 registers are dead now; reuse the same r registers.
    r0.x = b.x + v4.x*c0.x + v4.y*c1.x + v4.z*c2.x + v4.w*c3.x;
    r0.y = b.y + v4.x*c0.y + v4.y*c1.y + v4.z*c2.y + v4.w*c3.y;
    r0.z = b.z + v4.x*c0.z + v4.y*c1.z + v4.z*c2.z + v4.w*c3.z;
    r0.w = b.w + v4.x*c0.w + v4.y*c1.w + v4.z*c2.w + v4.w*c3.w;

    r1.x = b.x + v5.x*c0.x + v5.y*c1.x + v5.z*c2.x + v5.w*c3.x;
    r1.y = b.y + v5.x*c0.y + v5.y*c1.y + v5.z*c2.y + v5.w*c3.y;
    r1.z = b.z + v5.x*c0.z + v5.y*c1.z + v5.z*c2.z + v5.w*c3.z;
    r1.w = b.w + v5.x*c0.w + v5.y*c1.w + v5.z*c2.w + v5.w*c3.w;

    r2.x = b.x + v6.x*c0.x + v6.y*c1.x + v6.z*c2.x + v6.w*c3.x;
    r2.y = b.y + v6.x*c0.y + v6.y*c1.y + v6.z*c2.y + v6.w*c3.y;
    r2.z = b.z + v6.x*c0.z + v6.y*c1.z + v6.z*c2.z + v6.w*c3.z;
    r2.w = b.w + v6.x*c0.w + v6.y*c1.w + v6.z*c2.w + v6.w*c3.w;

    r3.x = b.x + v7.x*c0.x + v7.y*c1.x + v7.z*c2.x + v7.w*c3.x;
    r3.y = b.y + v7.x*c0.y + v7.y*c1.y + v7.z*c2.y + v7.w*c3.y;
    r3.z = b.z + v7.x*c0.z + v7.y*c1.z + v7.z*c2.z + v7.w*c3.z;
    r3.w = b.w + v7.x*c0.w + v7.y*c1.w + v7.z*c2.w + v7.w*c3.w;

    __stcs(op + 4 * GROUPS, r0);
    __stcs(op + 5 * GROUPS, r1);
    __stcs(op + 6 * GROUPS, r2);
    __stcs(op + 7 * GROUPS, r3);
}

// ---------------------------------------------------------------------------
extern "C" void kernel_launch(void* const* d_in, const int* in_sizes, int n_in,
                              void* d_out, int out_size) {
    const float* x = nullptr;
    const float* factors = nullptr;
    const float* bias = nullptr;
    for (int i = 0; i < n_in; i++) {
        if (in_sizes[i] == TOKENS * NCOLS)            x = (const float*)d_in[i];
        else if (in_sizes[i] == DEPTH * PAIRS * 4)    factors = (const float*)d_in[i];
        else if (in_sizes[i] == NCOLS)                bias = (const float*)d_in[i];
    }

    // Kernel 1: 4096 threads = 1 per (group, column), across 128 SMs.
    butterfly_precompute<<<128, 32>>>((const float4*)factors);

    // Kernel 2: (4, 1024) = 4096 blocks, 8 tokens per thread.
    dim3 grid(GROUPS / 256, TOKENS / T_PER);
    butterfly_apply<<<grid, 256>>>((const float4*)x,
                                   (const float4*)bias,
                                   (float4*)d_out);
}